// round 12
// baseline (speedup 1.0000x reference)
#include <cuda_runtime.h>
#include <math.h>

#define RPB 16          // rows per block
#define TPB 416         // 13 full warps; 400 quads -> 1 quad/thread, balanced
#define C_BBOX  5.0f
#define C_GIOU  2.0f
#define BIGV    10000.0f

__device__ __forceinline__ float clamp01(float x) {
    return fminf(fmaxf(x, 0.f), 1.f);
}

// one (row r, 4-target quad) cost evaluation
__device__ __forceinline__ void eval4(
    const float4 rb0, const float4 rb1, const float ra,
    const float4* raw, const float4* xy, const float* ta, const int* id,
    const float* s_prob_row, float* res)
{
    #pragma unroll
    for (int k = 0; k < 4; k++) {
        float p  = s_prob_row[id[k]];
        float d0 = rb0.x - raw[k].x, d1 = rb0.y - raw[k].y;
        float d2 = rb0.z - raw[k].z, d3 = rb0.w - raw[k].w;
        float l1 = (fabsf(d0) + fabsf(d1)) + (fabsf(d2) + fabsf(d3));
        float ltx = fmaxf(rb1.x, xy[k].x), lty = fmaxf(rb1.y, xy[k].y);
        float rbx = fminf(rb1.z, xy[k].z), rby = fminf(rb1.w, xy[k].w);
        float wx  = fmaxf(rbx - ltx, 0.f), wy = fmaxf(rby - lty, 0.f);
        float inter = wx * wy;
        float uni   = (ra + ta[k]) - inter;
        float lcx = fminf(rb1.x, xy[k].x), lcy = fminf(rb1.y, xy[k].y);
        float hcx = fmaxf(rb1.z, xy[k].z), hcy = fmaxf(rb1.w, xy[k].w);
        float areac = (hcx - lcx) * (hcy - lcy);
        // iou + uni/areac = (inter*areac + uni^2) / (uni*areac)
        float num = fmaf(uni, uni, inter * areac);
        float t   = __fdividef(num, uni * areac);
        float cost = fmaf(C_BBOX, l1, C_GIOU - p) - C_GIOU * t;
        if (cost != cost) cost = BIGV;                 // NaN -> BIG (before clamp!)
        else cost = fminf(fmaxf(cost, -BIGV), BIGV);   // +/-inf -> +/-BIG
        res[k] = cost;
    }
}

__global__ __launch_bounds__(TPB) void matcher_kernel(
    const float* __restrict__ logits,   // [BQ, NC]
    const float* __restrict__ pboxes,   // [BQ, 4]
    const int*   __restrict__ tids,     // [N]
    const float* __restrict__ tboxes,   // [N, 4]
    float* __restrict__ out,            // [BQ, N]
    int BQ, int NC, int N)
{
    extern __shared__ char smem_raw[];
    // layout: traw [N]float4 | rbox [RPB*3]float4 | prob [RPB*NC]f32 | tid [N]i32
    float4* s_traw = (float4*)smem_raw;
    float4* s_rbox = (float4*)(smem_raw + 16 * N);
    float*  s_prob = (float*) (smem_raw + 16 * N + RPB * 48);
    int*    s_tid  = (int*)   (smem_raw + 16 * N + RPB * 48 + RPB * NC * 4);

    const int tid  = threadIdx.x;
    const int row0 = blockIdx.x * RPB;

    // ---- stage raw targets + ids into SMEM ----
    for (int i = tid; i < N; i += TPB) {
        s_traw[i] = ((const float4*)tboxes)[i];
        s_tid[i]  = tids[i];
    }

    // ---- per-row softmax + pred-box precompute ----
    const int warp   = tid >> 5;
    const int lane   = tid & 31;
    const int nwarps = TPB / 32;
    for (int rr = warp; rr < RPB; rr += nwarps) {
        int row = row0 + rr;
        if (row >= BQ) continue;
        const float* lg = logits + (size_t)row * NC;
        float v[4];                       // supports NC <= 128
        const int cnt = (NC + 31) >> 5;
        float m = -1e30f;
        for (int k = 0; k < cnt; k++) {
            int idx = lane + (k << 5);
            v[k] = (idx < NC) ? lg[idx] : -1e30f;
            m = fmaxf(m, v[k]);
        }
        #pragma unroll
        for (int o = 16; o; o >>= 1) m = fmaxf(m, __shfl_xor_sync(0xFFFFFFFFu, m, o));
        float s = 0.f;
        for (int k = 0; k < cnt; k++) {
            int idx = lane + (k << 5);
            v[k] = (idx < NC) ? __expf(v[k] - m) : 0.f;
            s += v[k];
        }
        #pragma unroll
        for (int o = 16; o; o >>= 1) s += __shfl_xor_sync(0xFFFFFFFFu, s, o);
        float inv = 1.0f / s;
        for (int k = 0; k < cnt; k++) {
            int idx = lane + (k << 5);
            if (idx < NC) s_prob[rr * NC + idx] = v[k] * inv;
        }
        if (lane == 0) {
            float4 pb = ((const float4*)pboxes)[row];
            float cx = clamp01(pb.x), cy = clamp01(pb.y);
            float w  = clamp01(pb.z), h  = clamp01(pb.w);
            s_rbox[rr * 3 + 0] = pb;  // raw cxcywh for L1
            float4 xy;
            xy.x = cx - 0.5f * w; xy.y = cy - 0.5f * h;
            xy.z = cx + 0.5f * w; xy.w = cy + 0.5f * h;
            s_rbox[rr * 3 + 1] = xy;  // clamped xyxy
            float4 ar; ar.x = w * h; ar.y = 0.f; ar.z = 0.f; ar.w = 0.f;
            s_rbox[rr * 3 + 2] = ar;  // pred area
        }
    }
    __syncthreads();

    const int rmax = min(RPB, BQ - row0);
    const int nq   = N >> 2;   // target quads (400 for N=1600)

    // ---- main loop: 1 quad (4 targets) per thread, rows inner, STG.128 ----
    for (int q = tid; q < nq; q += TPB) {
        float4 raw[4], xy[4];
        float  ta[4];
        int    id[4];
        #pragma unroll
        for (int k = 0; k < 4; k++) {
            int c = 4 * q + k;
            raw[k] = s_traw[c];
            id[k]  = s_tid[c];
            float cx = clamp01(raw[k].x), cy = clamp01(raw[k].y);
            float w  = clamp01(raw[k].z), h  = clamp01(raw[k].w);
            xy[k].x = cx - 0.5f * w; xy[k].y = cy - 0.5f * h;
            xy[k].z = cx + 0.5f * w; xy[k].w = cy + 0.5f * h;
            ta[k]   = w * h;
        }

        if (rmax == RPB) {
            // constant trip count: clean unroll, no dynamic remainder
            #pragma unroll 4
            for (int r = 0; r < RPB; r++) {
                float res[4];
                eval4(s_rbox[r * 3 + 0], s_rbox[r * 3 + 1], s_rbox[r * 3 + 2].x,
                      raw, xy, ta, id, s_prob + r * NC, res);
                float4 v4; v4.x = res[0]; v4.y = res[1]; v4.z = res[2]; v4.w = res[3];
                ((float4*)out)[(size_t)(row0 + r) * nq + q] = v4;
            }
        } else {
            for (int r = 0; r < rmax; r++) {
                float res[4];
                eval4(s_rbox[r * 3 + 0], s_rbox[r * 3 + 1], s_rbox[r * 3 + 2].x,
                      raw, xy, ta, id, s_prob + r * NC, res);
                float4 v4; v4.x = res[0]; v4.y = res[1]; v4.z = res[2]; v4.w = res[3];
                ((float4*)out)[(size_t)(row0 + r) * nq + q] = v4;
            }
        }
    }

    // ---- scalar tail if N not divisible by 4 ----
    for (int c = (nq << 2) + tid; c < N; c += TPB) {
        float4 raw = s_traw[c];
        int    id  = s_tid[c];
        float cx = clamp01(raw.x), cy = clamp01(raw.y);
        float w  = clamp01(raw.z), h  = clamp01(raw.w);
        float4 xy;
        xy.x = cx - 0.5f * w; xy.y = cy - 0.5f * h;
        xy.z = cx + 0.5f * w; xy.w = cy + 0.5f * h;
        float ta = w * h;
        for (int r = 0; r < rmax; r++) {
            const float4 rb0 = s_rbox[r * 3 + 0];
            const float4 rb1 = s_rbox[r * 3 + 1];
            const float  ra  = s_rbox[r * 3 + 2].x;
            float p  = s_prob[r * NC + id];
            float l1 = fabsf(rb0.x - raw.x) + fabsf(rb0.y - raw.y)
                     + fabsf(rb0.z - raw.z) + fabsf(rb0.w - raw.w);
            float ltx = fmaxf(rb1.x, xy.x), lty = fmaxf(rb1.y, xy.y);
            float rbx = fminf(rb1.z, xy.z), rby = fminf(rb1.w, xy.w);
            float wx  = fmaxf(rbx - ltx, 0.f), wy = fmaxf(rby - lty, 0.f);
            float inter = wx * wy;
            float uni   = (ra + ta) - inter;
            float lcx = fminf(rb1.x, xy.x), lcy = fminf(rb1.y, xy.y);
            float hcx = fmaxf(rb1.z, xy.z), hcy = fmaxf(rb1.w, xy.w);
            float areac = (hcx - lcx) * (hcy - lcy);
            float num = fmaf(uni, uni, inter * areac);
            float t   = __fdividef(num, uni * areac);
            float cost = fmaf(C_BBOX, l1, C_GIOU - p) - C_GIOU * t;
            if (cost != cost) cost = BIGV;
            else cost = fminf(fmaxf(cost, -BIGV), BIGV);
            out[(size_t)(row0 + r) * N + c] = cost;
        }
    }
}

extern "C" void kernel_launch(void* const* d_in, const int* in_sizes, int n_in,
                              void* d_out, int out_size)
{
    const float* logits = (const float*)d_in[0];   // [B,Q,NC]
    const float* pboxes = (const float*)d_in[1];   // [B,Q,4]
    const int*   tids   = (const int*)  d_in[2];   // [N]
    const float* tboxes = (const float*)d_in[3];   // [N,4]
    float* out = (float*)d_out;

    const int N  = in_sizes[2];
    const int BQ = in_sizes[1] / 4;
    const int NC = in_sizes[0] / BQ;

    // traw + rbox + prob + tid  = 16N + 768 + 4*RPB*NC + 4N  (~38.6 KB)
    const int smem = 16 * N + RPB * 48 + RPB * NC * 4 + 4 * N;

    const int grid = (BQ + RPB - 1) / RPB;
    matcher_kernel<<<grid, TPB, smem>>>(logits, pboxes, tids, tboxes, out,
                                        BQ, NC, N);
    (void)n_in; (void)out_size;
}

// round 16
// speedup vs baseline: 1.2104x; 1.2104x over previous
#include <cuda_runtime.h>
#include <math.h>

#define RPB 16          // rows per block
#define TPB 800         // 25 full warps; 800 target-pairs -> 1 pair/thread
#define C_BBOX  5.0f
#define C_GIOU  2.0f
#define BIGV    10000.0f

__device__ __forceinline__ float clamp01(float x) {
    return fminf(fmaxf(x, 0.f), 1.f);
}

__global__ __launch_bounds__(TPB) void matcher_kernel(
    const float* __restrict__ logits,   // [BQ, NC]
    const float* __restrict__ pboxes,   // [BQ, 4]
    const int*   __restrict__ tids,     // [N]
    const float* __restrict__ tboxes,   // [N, 4]
    float* __restrict__ out,            // [BQ, N]
    int BQ, int NC, int N)
{
    extern __shared__ char smem_raw[];
    // layout: traw [N]float4 | rbox [RPB*3]float4 | prob [RPB*NC]f32 | tid [N]i32
    float4* s_traw = (float4*)smem_raw;
    float4* s_rbox = (float4*)(smem_raw + 16 * N);
    float*  s_prob = (float*) (smem_raw + 16 * N + RPB * 48);
    int*    s_tid  = (int*)   (smem_raw + 16 * N + RPB * 48 + RPB * NC * 4);

    const int tid  = threadIdx.x;
    const int row0 = blockIdx.x * RPB;

    // ---- stage raw targets + ids into SMEM ----
    for (int i = tid; i < N; i += TPB) {
        s_traw[i] = ((const float4*)tboxes)[i];
        s_tid[i]  = tids[i];
    }

    // ---- per-row softmax + pred-box precompute ----
    const int warp   = tid >> 5;
    const int lane   = tid & 31;
    const int nwarps = TPB / 32;
    for (int rr = warp; rr < RPB; rr += nwarps) {
        int row = row0 + rr;
        if (row >= BQ) continue;
        const float* lg = logits + (size_t)row * NC;
        float v[4];                       // supports NC <= 128
        const int cnt = (NC + 31) >> 5;
        float m = -1e30f;
        for (int k = 0; k < cnt; k++) {
            int idx = lane + (k << 5);
            v[k] = (idx < NC) ? lg[idx] : -1e30f;
            m = fmaxf(m, v[k]);
        }
        #pragma unroll
        for (int o = 16; o; o >>= 1) m = fmaxf(m, __shfl_xor_sync(0xFFFFFFFFu, m, o));
        float s = 0.f;
        for (int k = 0; k < cnt; k++) {
            int idx = lane + (k << 5);
            v[k] = (idx < NC) ? __expf(v[k] - m) : 0.f;
            s += v[k];
        }
        #pragma unroll
        for (int o = 16; o; o >>= 1) s += __shfl_xor_sync(0xFFFFFFFFu, s, o);
        float inv = 1.0f / s;
        for (int k = 0; k < cnt; k++) {
            int idx = lane + (k << 5);
            if (idx < NC) s_prob[rr * NC + idx] = v[k] * inv;
        }
        if (lane == 0) {
            float4 pb = ((const float4*)pboxes)[row];
            float cx = clamp01(pb.x), cy = clamp01(pb.y);
            float w  = clamp01(pb.z), h  = clamp01(pb.w);
            s_rbox[rr * 3 + 0] = pb;  // raw cxcywh for L1
            float4 xy;
            xy.x = cx - 0.5f * w; xy.y = cy - 0.5f * h;
            xy.z = cx + 0.5f * w; xy.w = cy + 0.5f * h;
            s_rbox[rr * 3 + 1] = xy;  // clamped xyxy
            float4 ar; ar.x = w * h; ar.y = 0.f; ar.z = 0.f; ar.w = 0.f;
            s_rbox[rr * 3 + 2] = ar;  // pred area
        }
    }
    __syncthreads();

    const int rmax = min(RPB, BQ - row0);
    const int np   = N >> 1;   // target pairs (800 for N=1600)

    // ---- main loop: 1 pair (2 targets) per thread, rows inner, STG.64 ----
    for (int q = tid; q < np; q += TPB) {
        float4 raw[2], xy[2];
        float  ta[2];
        int    id[2];
        #pragma unroll
        for (int k = 0; k < 2; k++) {
            int c = 2 * q + k;
            raw[k] = s_traw[c];
            id[k]  = s_tid[c];
            float cx = clamp01(raw[k].x), cy = clamp01(raw[k].y);
            float w  = clamp01(raw[k].z), h  = clamp01(raw[k].w);
            xy[k].x = cx - 0.5f * w; xy[k].y = cy - 0.5f * h;
            xy[k].z = cx + 0.5f * w; xy[k].w = cy + 0.5f * h;
            ta[k]   = w * h;
        }

        #pragma unroll 4
        for (int r = 0; r < rmax; r++) {
            const float4 rb0 = s_rbox[r * 3 + 0]; // raw cxcywh
            const float4 rb1 = s_rbox[r * 3 + 1]; // clamped xyxy
            const float  ra  = s_rbox[r * 3 + 2].x;
            const float* pr  = s_prob + r * NC;
            float res[2];
            #pragma unroll
            for (int k = 0; k < 2; k++) {
                float p  = pr[id[k]];
                float d0 = rb0.x - raw[k].x, d1 = rb0.y - raw[k].y;
                float d2 = rb0.z - raw[k].z, d3 = rb0.w - raw[k].w;
                float l1 = (fabsf(d0) + fabsf(d1)) + (fabsf(d2) + fabsf(d3));
                float ltx = fmaxf(rb1.x, xy[k].x), lty = fmaxf(rb1.y, xy[k].y);
                float rbx = fminf(rb1.z, xy[k].z), rby = fminf(rb1.w, xy[k].w);
                float wx  = fmaxf(rbx - ltx, 0.f), wy = fmaxf(rby - lty, 0.f);
                float inter = wx * wy;
                float uni   = (ra + ta[k]) - inter;
                float lcx = fminf(rb1.x, xy[k].x), lcy = fminf(rb1.y, xy[k].y);
                float hcx = fmaxf(rb1.z, xy[k].z), hcy = fmaxf(rb1.w, xy[k].w);
                float areac = (hcx - lcx) * (hcy - lcy);
                // iou + uni/areac = (inter*areac + uni^2) / (uni*areac)
                float num = fmaf(uni, uni, inter * areac);
                float t   = __fdividef(num, uni * areac);
                float cost = fmaf(C_BBOX, l1, C_GIOU - p) - C_GIOU * t;
                if (cost != cost) cost = BIGV;                 // NaN -> BIG (before clamp!)
                else cost = fminf(fmaxf(cost, -BIGV), BIGV);   // +/-inf -> +/-BIG
                res[k] = cost;
            }
            float2 v2; v2.x = res[0]; v2.y = res[1];
            ((float2*)out)[(size_t)(row0 + r) * np + q] = v2;
        }
    }

    // ---- scalar tail if N odd ----
    for (int c = (np << 1) + tid; c < N; c += TPB) {
        float4 raw = s_traw[c];
        int    id  = s_tid[c];
        float cx = clamp01(raw.x), cy = clamp01(raw.y);
        float w  = clamp01(raw.z), h  = clamp01(raw.w);
        float4 xy;
        xy.x = cx - 0.5f * w; xy.y = cy - 0.5f * h;
        xy.z = cx + 0.5f * w; xy.w = cy + 0.5f * h;
        float ta = w * h;
        for (int r = 0; r < rmax; r++) {
            const float4 rb0 = s_rbox[r * 3 + 0];
            const float4 rb1 = s_rbox[r * 3 + 1];
            const float  ra  = s_rbox[r * 3 + 2].x;
            float p  = s_prob[r * NC + id];
            float l1 = fabsf(rb0.x - raw.x) + fabsf(rb0.y - raw.y)
                     + fabsf(rb0.z - raw.z) + fabsf(rb0.w - raw.w);
            float ltx = fmaxf(rb1.x, xy.x), lty = fmaxf(rb1.y, xy.y);
            float rbx = fminf(rb1.z, xy.z), rby = fminf(rb1.w, xy.w);
            float wx  = fmaxf(rbx - ltx, 0.f), wy = fmaxf(rby - lty, 0.f);
            float inter = wx * wy;
            float uni   = (ra + ta) - inter;
            float lcx = fminf(rb1.x, xy.x), lcy = fminf(rb1.y, xy.y);
            float hcx = fmaxf(rb1.z, xy.z), hcy = fmaxf(rb1.w, xy.w);
            float areac = (hcx - lcx) * (hcy - lcy);
            float num = fmaf(uni, uni, inter * areac);
            float t   = __fdividef(num, uni * areac);
            float cost = fmaf(C_BBOX, l1, C_GIOU - p) - C_GIOU * t;
            if (cost != cost) cost = BIGV;
            else cost = fminf(fmaxf(cost, -BIGV), BIGV);
            out[(size_t)(row0 + r) * N + c] = cost;
        }
    }
}

extern "C" void kernel_launch(void* const* d_in, const int* in_sizes, int n_in,
                              void* d_out, int out_size)
{
    const float* logits = (const float*)d_in[0];   // [B,Q,NC]
    const float* pboxes = (const float*)d_in[1];   // [B,Q,4]
    const int*   tids   = (const int*)  d_in[2];   // [N]
    const float* tboxes = (const float*)d_in[3];   // [N,4]
    float* out = (float*)d_out;

    const int N  = in_sizes[2];
    const int BQ = in_sizes[1] / 4;
    const int NC = in_sizes[0] / BQ;

    // traw + rbox + prob + tid  = 16N + 768 + 4*RPB*NC + 4N  (~38.6 KB)
    const int smem = 16 * N + RPB * 48 + RPB * NC * 4 + 4 * N;

    const int grid = (BQ + RPB - 1) / RPB;
    matcher_kernel<<<grid, TPB, smem>>>(logits, pboxes, tids, tboxes, out,
                                        BQ, NC, N);
    (void)n_in; (void)out_size;
}